// round 7
// baseline (speedup 1.0000x reference)
#include <cuda_runtime.h>
#include <cuda_bf16.h>

#define NF   256     // feature dim
#define DEG  32      // neighbors per node
#define MM   33      // subgraph size (target + neighbors)
#define BMAX 10240   // max batch (actual B=10000)
#define WPB  8       // warps per block in weights_kernel

// Scratch (allocation-free: __device__ globals)
__device__ __align__(16) float g_mix[(size_t)BMAX * NF];
__device__ float g_c0[BMAX];
__device__ float g_w[(size_t)BMAX * MM];
__device__ int   g_sid[(size_t)BMAX * MM];

// ---------------------------------------------------------------------------
// Kernel A1: per-target weights via hash-based membership.
// One warp per target. 64-slot open-addressing hash of the 33 subgraph ids;
// each adjacency entry probes once instead of scanning 33 columns.
// ---------------------------------------------------------------------------
__global__ void __launch_bounds__(256) weights_kernel(
    const int* __restrict__ adj,    // [N_NODES, DEG]
    const int* __restrict__ bn,     // [B]
    int B)
{
    __shared__ int   tbl_id[WPB][64];
    __shared__ unsigned char tbl_col[WPB][64];
    __shared__ int   s_ids[WPB][MM];
    __shared__ unsigned long long s_mask[WPB][MM];
    __shared__ float s_c[WPB][MM];
    __shared__ unsigned long long s_vm[WPB];

    const int w    = threadIdx.x >> 5;
    const int lane = threadIdx.x & 31;
    const int b    = blockIdx.x * WPB + w;
    if (b >= B) return;                      // whole warp exits together

    const int v = bn[b];
    tbl_id[w][lane]      = -1;
    tbl_id[w][lane + 32] = -1;
    s_ids[w][lane + 1] = adj[(size_t)v * DEG + lane];
    if (lane == 0) s_ids[w][0] = v;
    __syncwarp();

    // serial hash insert + dedup (lane 0): first occurrence wins
    if (lane == 0) {
        unsigned long long vm = 0ull;
        for (int j = 0; j < MM; j++) {
            int id = s_ids[w][j];
            unsigned h = ((unsigned)id * 0x9E3779B1u) >> 26;
            bool dup = false;
            while (true) {
                int slot = tbl_id[w][h];
                if (slot == id) { dup = true; break; }
                if (slot == -1) {
                    tbl_id[w][h]  = id;
                    tbl_col[w][h] = (unsigned char)j;
                    break;
                }
                h = (h + 1) & 63;
            }
            if (!dup) vm |= 1ull << j;
        }
        s_vm[w] = vm;
    }
    __syncwarp();
    const unsigned long long vm = s_vm[w];

    // membership: iteration i = row; lane = adjacency entry k
    for (int i = 0; i < MM; i++) {
        int sid = s_ids[w][i];
        int a   = adj[(size_t)sid * DEG + lane];     // coalesced 128B row
        unsigned h = ((unsigned)a * 0x9E3779B1u) >> 26;
        int col = -1;
        while (true) {
            int slot = tbl_id[w][h];
            if (slot == a) { col = tbl_col[w][h]; break; }
            if (slot == -1) break;
            h = (h + 1) & 63;
        }
        unsigned lo = __reduce_or_sync(0xffffffffu,
                        (col >= 0 && col < 32) ? (1u << col) : 0u);
        unsigned hi = __reduce_or_sync(0xffffffffu,
                        (col == 32) ? 1u : 0u);
        if (lane == 0) {
            unsigned long long m = (unsigned long long)lo |
                                   ((unsigned long long)hi << 32);
            m = ((vm >> i) & 1ull) ? (m & vm) : 0ull;
            s_mask[w][i] = m;
        }
    }
    __syncwarp();

    // in-degrees per column -> c = 1/sqrt(max(deg,1))
    for (int j = lane; j < MM; j += 32) {
        int cnt = 0;
        #pragma unroll
        for (int i = 0; i < MM; i++)
            cnt += (int)((s_mask[w][i] >> j) & 1ull);
        s_c[w][j] = rsqrtf((float)(cnt < 1 ? 1 : cnt));
    }
    __syncwarp();

    // w_src[i] = c_i * sum_{j in row_i} c_j   (rows are sparse)
    for (int i = lane; i < MM; i += 32) {
        unsigned long long m = s_mask[w][i];
        float sum = 0.0f;
        while (m) {
            int j = __ffsll((long long)m) - 1;
            sum += s_c[w][j];
            m &= (m - 1);
        }
        g_w[(size_t)b * MM + i]   = s_c[w][i] * sum;
        g_sid[(size_t)b * MM + i] = s_ids[w][i];
    }
    if (lane == 0) g_c0[b] = s_c[w][0];
}

// ---------------------------------------------------------------------------
// Kernel A2: mix[b] = sum_i w[b,i] * feat[sid[b,i]]  — pure streaming gather.
// 4 targets per 256-thread CTA; 64 threads (16 float4 lanes x 4) per target.
// ---------------------------------------------------------------------------
#define GRP 4
__global__ void __launch_bounds__(256) mix_kernel(
    const float* __restrict__ feat, int B)
{
    __shared__ float s_w[GRP][MM];
    __shared__ int   s_id[GRP][MM];

    const int t  = threadIdx.x;
    const int b0 = blockIdx.x * GRP;

    for (int idx = t; idx < GRP * MM; idx += 256) {
        int g = idx / MM, i = idx - g * MM;
        int b = b0 + g;
        if (b < B) {
            s_w[g][i]  = g_w[(size_t)b * MM + i];
            s_id[g][i] = g_sid[(size_t)b * MM + i];
        }
    }
    __syncthreads();

    const int g = t >> 6;
    const int j = t & 63;        // float4 column index
    const int b = b0 + g;
    if (b >= B) return;

    float4 acc = make_float4(0.f, 0.f, 0.f, 0.f);
    for (int i = 0; i < MM; i++) {
        float  wv = s_w[g][i];
        float4 f4 = *reinterpret_cast<const float4*>(
                        &feat[(size_t)s_id[g][i] * NF + j * 4]);
        acc.x = fmaf(wv, f4.x, acc.x);
        acc.y = fmaf(wv, f4.y, acc.y);
        acc.z = fmaf(wv, f4.z, acc.z);
        acc.w = fmaf(wv, f4.w, acc.w);
    }
    *reinterpret_cast<float4*>(&g_mix[(size_t)b * NF + j * 4]) = acc;
}

// ---------------------------------------------------------------------------
// Kernel B: out = relu(mix @ W + c0 * feat[batch_nodes])
// 64x128 tile, BK=16, 256 threads, 8x4 microtile (R5 config),
// + smem double buffering: ONE barrier per K-iter, prefetch overlaps compute.
// ---------------------------------------------------------------------------
#define BM 64
#define BN 128
#define BK 16

__global__ void __launch_bounds__(256) gemm_kernel(
    const float* __restrict__ W,      // [NF, NF] row-major (k, n)
    const float* __restrict__ feat,   // [N_NODES, NF]
    const int*   __restrict__ bn,     // [B]
    float*       __restrict__ out,    // [B, NF]
    int B)
{
    __shared__ __align__(16) float sA[2][BK][BM];   // transposed A tiles
    __shared__ __align__(16) float sB[2][BK][BN];

    const int tid = threadIdx.x;
    const int bm0 = blockIdx.y * BM;
    const int bn0 = blockIdx.x * BN;
    const int ty  = tid >> 5;         // 0..7  -> rows ty*8 .. +7
    const int tx  = tid & 31;         // 0..31 -> cols tx*4 .. +3

    const int arow = tid >> 2;        // 0..63
    const int acol = (tid & 3) * 4;   // 0,4,8,12
    const int brow = tid >> 5;        // 0..7  (and +8)
    const int bcol = (tid & 31) * 4;  // 0..124

    const int  agr = bm0 + arow;
    const bool aok = (agr < B);
    const float* aP = &g_mix[(size_t)agr * NF + acol];
    const float* bP0 = &W[(size_t)brow * NF + bn0 + bcol];
    const float* bP1 = &W[(size_t)(brow + 8) * NF + bn0 + bcol];

    float acc[8][4];
    #pragma unroll
    for (int m = 0; m < 8; m++)
        #pragma unroll
        for (int n = 0; n < 4; n++) acc[m][n] = 0.0f;

    // prefetch first K-tile into registers
    float4 nA = aok ? *reinterpret_cast<const float4*>(aP)
                    : make_float4(0.f, 0.f, 0.f, 0.f);
    float4 nB0 = *reinterpret_cast<const float4*>(bP0);
    float4 nB1 = *reinterpret_cast<const float4*>(bP1);

    #pragma unroll 1
    for (int kk = 0; kk < NF; kk += BK) {
        const int s = (kk / BK) & 1;
        // commit current tile to smem stage s
        sA[s][acol + 0][arow] = nA.x;
        sA[s][acol + 1][arow] = nA.y;
        sA[s][acol + 2][arow] = nA.z;
        sA[s][acol + 3][arow] = nA.w;
        *reinterpret_cast<float4*>(&sB[s][brow][bcol])     = nB0;
        *reinterpret_cast<float4*>(&sB[s][brow + 8][bcol]) = nB1;
        __syncthreads();

        // prefetch next tile (overlaps the compute below)
        if (kk + BK < NF) {
            nA = aok ? *reinterpret_cast<const float4*>(aP + kk + BK)
                     : make_float4(0.f, 0.f, 0.f, 0.f);
            nB0 = *reinterpret_cast<const float4*>(bP0 + (size_t)(kk + BK) * NF);
            nB1 = *reinterpret_cast<const float4*>(bP1 + (size_t)(kk + BK) * NF);
        }

        #pragma unroll
        for (int k = 0; k < BK; k++) {
            float4 ra0 = *reinterpret_cast<const float4*>(&sA[s][k][ty * 8 + 0]);
            float4 ra1 = *reinterpret_cast<const float4*>(&sA[s][k][ty * 8 + 4]);
            float4 rb  = *reinterpret_cast<const float4*>(&sB[s][k][tx * 4]);
            float am[8] = {ra0.x, ra0.y, ra0.z, ra0.w, ra1.x, ra1.y, ra1.z, ra1.w};
            float bv[4] = {rb.x, rb.y, rb.z, rb.w};
            #pragma unroll
            for (int m = 0; m < 8; m++)
                #pragma unroll
                for (int n = 0; n < 4; n++)
                    acc[m][n] = fmaf(am[m], bv[n], acc[m][n]);
        }
        // no second barrier: next iteration writes the OTHER stage
    }

    // epilogue: relu(acc + c0[row] * feat[bn[row]][col]), float4 stores
    #pragma unroll
    for (int m = 0; m < 8; m++) {
        int gr = bm0 + ty * 8 + m;
        if (gr >= B) continue;
        int   node = bn[gr];
        float cc   = g_c0[gr];
        int   gc   = bn0 + tx * 4;
        float4 h4 = *reinterpret_cast<const float4*>(
                        &feat[(size_t)node * NF + gc]);
        float4 r;
        r.x = fmaxf(acc[m][0] + cc * h4.x, 0.0f);
        r.y = fmaxf(acc[m][1] + cc * h4.y, 0.0f);
        r.z = fmaxf(acc[m][2] + cc * h4.z, 0.0f);
        r.w = fmaxf(acc[m][3] + cc * h4.w, 0.0f);
        *reinterpret_cast<float4*>(&out[(size_t)gr * NF + gc]) = r;
    }
}

// ---------------------------------------------------------------------------
extern "C" void kernel_launch(void* const* d_in, const int* in_sizes, int n_in,
                              void* d_out, int out_size)
{
    const float* feat = (const float*)d_in[0];   // node_features [50000,256]
    const float* W    = (const float*)d_in[1];   // weight [256,256]
    const int*   adj  = (const int*)d_in[2];     // adj [50000,32]
    const int*   bn   = (const int*)d_in[3];     // batch_nodes [B]
    float*       out  = (float*)d_out;

    const int B = in_sizes[3];

    weights_kernel<<<(B + WPB - 1) / WPB, 256>>>(adj, bn, B);
    mix_kernel<<<(B + GRP - 1) / GRP, 256>>>(feat, B);

    dim3 grid(NF / BN, (B + BM - 1) / BM);
    gemm_kernel<<<grid, 256>>>(W, feat, bn, out, B);
}

// round 8
// speedup vs baseline: 1.5584x; 1.5584x over previous
#include <cuda_runtime.h>
#include <cuda_bf16.h>

#define NF   256     // feature dim
#define DEG  32      // neighbors per node
#define MM   33      // subgraph size (target + neighbors)
#define BMAX 10240   // max batch (actual B=10000)

// Scratch (allocation-free: __device__ globals)
__device__ __align__(16) float g_mix[(size_t)BMAX * NF];
__device__ float g_c0[BMAX];

__device__ __forceinline__ unsigned f2tf32(float f) {
    unsigned u;
    asm("cvt.rna.tf32.f32 %0, %1;" : "=r"(u) : "f"(f));
    return u;
}

__device__ __forceinline__ void mma_tf32_16n8k8(
    float d[4], const unsigned a[4], const unsigned b[2], const float c[4])
{
    asm volatile(
        "mma.sync.aligned.m16n8k8.row.col.f32.tf32.tf32.f32 "
        "{%0,%1,%2,%3}, {%4,%5,%6,%7}, {%8,%9}, {%10,%11,%12,%13};\n"
        : "=f"(d[0]), "=f"(d[1]), "=f"(d[2]), "=f"(d[3])
        : "r"(a[0]), "r"(a[1]), "r"(a[2]), "r"(a[3]),
          "r"(b[0]), "r"(b[1]),
          "f"(c[0]), "f"(c[1]), "f"(c[2]), "f"(c[3]));
}

// ---------------------------------------------------------------------------
// Kernel A: per-target subgraph construction + weighted feature mix
// (R5 structure; phase 3 membership uses int4 register loads + single
//  per-row s32 ballot instead of per-k redundant compares)
// ---------------------------------------------------------------------------
__global__ void __launch_bounds__(256) subgraph_kernel(
    const float* __restrict__ feat,   // [N_NODES, NF]
    const int*   __restrict__ adj,    // [N_NODES, DEG]
    const int*   __restrict__ bn,     // [B]
    int B)
{
    __shared__ int   s_ids[MM];
    __shared__ __align__(16) int s_adj[MM][DEG];
    __shared__ unsigned long long s_row[MM];   // adjacency bitmask rows (bits 0..32)
    __shared__ int   s_valid[MM];
    __shared__ float s_c[MM];
    __shared__ float s_w[MM];
    __shared__ __align__(16) float4 s_acc[4][64];   // per-quad partial mix

    const int b = blockIdx.x;
    const int t = threadIdx.x;

    // ---- phase 1: subgraph node ids s = [v, adj[v]] ----
    const int v = bn[b];
    if (t == 0)  s_ids[0] = v;
    if (t < DEG) s_ids[1 + t] = adj[(size_t)v * DEG + t];
    __syncthreads();

    // ---- phase 2: gather adjacency rows (int4, strided: 264 > 256) ----
    for (int idx = t; idx < MM * (DEG / 4); idx += 256) {
        int i = idx >> 3, q = idx & 7;
        int4 a4 = *reinterpret_cast<const int4*>(
                      &adj[(size_t)s_ids[i] * DEG + q * 4]);
        *reinterpret_cast<int4*>(&s_adj[i][q * 4]) = a4;
    }
    // dedup: valid[j] = no earlier occurrence of s[j]
    if (t < MM) {
        int sj = s_ids[t];
        int dup = 0;
        for (int i = 0; i < t; i++) dup |= (s_ids[i] == sj);
        s_valid[t] = !dup;
    }
    __syncthreads();

    // ---- phase 3: membership bitmasks; warp w handles rows i = w, w+8, ...
    {
        const int lane = t & 31;
        const int w    = t >> 5;
        const int sj   = s_ids[lane];
        const int s32  = s_ids[32];
        for (int i = w; i < MM; i += 8) {
            // column 32: one per-lane compare + ballot (not per-k redundant)
            int a_own = s_adj[i][lane];
            unsigned m32 = __ballot_sync(0xffffffffu, a_own == s32);
            // columns 0..31: int4 register loads, compare vs own sj
            bool bit = false;
            #pragma unroll
            for (int q = 0; q < 8; q++) {
                int4 a4 = *reinterpret_cast<const int4*>(&s_adj[i][q * 4]);
                bit |= (a4.x == sj) | (a4.y == sj) |
                       (a4.z == sj) | (a4.w == sj);
            }
            unsigned m = __ballot_sync(0xffffffffu, bit);
            if (lane == 0)
                s_row[i] = (unsigned long long)m |
                           (m32 ? (1ull << 32) : 0ull);
        }
    }
    __syncthreads();

    // ---- phase 4: validity masking ----
    if (t < MM) {
        unsigned long long vm = 0ull;
        #pragma unroll
        for (int i = 0; i < MM; i++)
            vm |= ((unsigned long long)(s_valid[i] != 0)) << i;
        s_row[t] = s_valid[t] ? (s_row[t] & vm) : 0ull;
    }
    __syncthreads();

    // ---- phase 5: in-degrees -> c = 1/sqrt(max(deg,1)) ----
    if (t < MM) {
        int cnt = 0;
        #pragma unroll
        for (int i = 0; i < MM; i++)
            cnt += (int)((s_row[i] >> t) & 1ull);
        float deg = (float)(cnt < 1 ? 1 : cnt);
        s_c[t] = rsqrtf(deg);
    }
    __syncthreads();

    // ---- phase 6: w_src[i] = c_i * sum_{j in row_i} c_j ----
    if (t < MM) {
        unsigned long long m = s_row[t];
        float sum = 0.0f;
        while (m) {
            int j = __ffsll((long long)m) - 1;
            sum += s_c[j];
            m &= (m - 1);
        }
        s_w[t] = s_c[t] * sum;
    }
    __syncthreads();

    // ---- phase 7: mix = sum_i w_i * feat[s_i]  (float4, quad-partitioned) ----
    {
        const int q = t >> 6;        // 0..3
        const int j = t & 63;        // float4 index within row
        float4 acc = make_float4(0.f, 0.f, 0.f, 0.f);
        for (int i = q; i < MM; i += 4) {
            float  wv = s_w[i];
            float4 f4 = *reinterpret_cast<const float4*>(
                            &feat[(size_t)s_ids[i] * NF + j * 4]);
            acc.x = fmaf(wv, f4.x, acc.x);
            acc.y = fmaf(wv, f4.y, acc.y);
            acc.z = fmaf(wv, f4.z, acc.z);
            acc.w = fmaf(wv, f4.w, acc.w);
        }
        s_acc[q][j] = acc;
    }
    __syncthreads();

    if (t < 64) {
        float4 a0 = s_acc[0][t], a1 = s_acc[1][t];
        float4 a2 = s_acc[2][t], a3 = s_acc[3][t];
        float4 r;
        r.x = (a0.x + a1.x) + (a2.x + a3.x);
        r.y = (a0.y + a1.y) + (a2.y + a3.y);
        r.z = (a0.z + a1.z) + (a2.z + a3.z);
        r.w = (a0.w + a1.w) + (a2.w + a3.w);
        *reinterpret_cast<float4*>(&g_mix[(size_t)b * NF + t * 4]) = r;
        if (t == 0) g_c0[b] = s_c[0];
    }
}

// ---------------------------------------------------------------------------
// Kernel B: out = relu(mix @ W + c0 * feat[batch_nodes])
// tf32 mma.sync m16n8k8. CTA tile 64x128, BK=16, 256 threads = 8 warps (2x4).
// Each warp computes 32x32 via 2x4 mma tiles.
// ---------------------------------------------------------------------------
#define BM 64
#define BN 128
#define BK 16

__global__ void __launch_bounds__(256) gemm_kernel(
    const float* __restrict__ W,      // [NF, NF] row-major (k, n)
    const float* __restrict__ feat,   // [N_NODES, NF]
    const int*   __restrict__ bn,     // [B]
    float*       __restrict__ out,    // [B, NF]
    int B)
{
    __shared__ __align__(16) unsigned sA[BK][BM + 4];   // tf32, transposed [k][m]
    __shared__ __align__(16) unsigned sB[BK][BN + 4];   // tf32, [k][n]

    const int tid  = threadIdx.x;
    const int lane = tid & 31;
    const int wid  = tid >> 5;
    const int bm0  = blockIdx.y * BM;
    const int bn0  = blockIdx.x * BN;

    const int wm  = wid >> 2;        // 0..1 : warp row (32 rows)
    const int wn  = wid & 3;         // 0..3 : warp col (32 cols)
    const int g   = lane >> 2;       // 0..7
    const int tig = lane & 3;        // 0..3

    // staging indices
    const int arow = tid >> 2;       // 0..63
    const int acol = (tid & 3) * 4;  // 0,4,8,12
    const int brow = tid >> 5;       // 0..7 (and +8)
    const int bcol = (tid & 31) * 4; // 0..124

    const int  agr = bm0 + arow;
    const bool aok = (agr < B);
    const float* aP  = &g_mix[(size_t)agr * NF + acol];
    const float* bP0 = &W[(size_t)brow * NF + bn0 + bcol];
    const float* bP1 = &W[(size_t)(brow + 8) * NF + bn0 + bcol];

    float acc[2][4][4];
    #pragma unroll
    for (int mt = 0; mt < 2; mt++)
        #pragma unroll
        for (int nt = 0; nt < 4; nt++)
            #pragma unroll
            for (int r = 0; r < 4; r++) acc[mt][nt][r] = 0.0f;

    // prefetch first K-tile
    float4 nA = aok ? *reinterpret_cast<const float4*>(aP)
                    : make_float4(0.f, 0.f, 0.f, 0.f);
    float4 nB0 = *reinterpret_cast<const float4*>(bP0);
    float4 nB1 = *reinterpret_cast<const float4*>(bP1);

    #pragma unroll 1
    for (int kk = 0; kk < NF; kk += BK) {
        // commit current tile (cvt to tf32)
        sA[acol + 0][arow] = f2tf32(nA.x);
        sA[acol + 1][arow] = f2tf32(nA.y);
        sA[acol + 2][arow] = f2tf32(nA.z);
        sA[acol + 3][arow] = f2tf32(nA.w);
        sB[brow][bcol + 0] = f2tf32(nB0.x);
        sB[brow][bcol + 1] = f2tf32(nB0.y);
        sB[brow][bcol + 2] = f2tf32(nB0.z);
        sB[brow][bcol + 3] = f2tf32(nB0.w);
        sB[brow + 8][bcol + 0] = f2tf32(nB1.x);
        sB[brow + 8][bcol + 1] = f2tf32(nB1.y);
        sB[brow + 8][bcol + 2] = f2tf32(nB1.z);
        sB[brow + 8][bcol + 3] = f2tf32(nB1.w);
        __syncthreads();

        // prefetch next K-tile (overlaps mma below)
        if (kk + BK < NF) {
            nA = aok ? *reinterpret_cast<const float4*>(aP + kk + BK)
                     : make_float4(0.f, 0.f, 0.f, 0.f);
            nB0 = *reinterpret_cast<const float4*>(bP0 + (size_t)(kk + BK) * NF);
            nB1 = *reinterpret_cast<const float4*>(bP1 + (size_t)(kk + BK) * NF);
        }

        #pragma unroll
        for (int ks = 0; ks < 2; ks++) {
            const int k0 = ks * 8;
            unsigned afr[2][4];
            #pragma unroll
            for (int mt = 0; mt < 2; mt++) {
                const int ar = wm * 32 + mt * 16;
                afr[mt][0] = sA[k0 + tig    ][ar + g    ];
                afr[mt][1] = sA[k0 + tig    ][ar + g + 8];
                afr[mt][2] = sA[k0 + tig + 4][ar + g    ];
                afr[mt][3] = sA[k0 + tig + 4][ar + g + 8];
            }
            unsigned bfr[4][2];
            #pragma unroll
            for (int nt = 0; nt < 4; nt++) {
                const int nb = wn * 32 + nt * 8;
                bfr[nt][0] = sB[k0 + tig    ][nb + g];
                bfr[nt][1] = sB[k0 + tig + 4][nb + g];
            }
            #pragma unroll
            for (int mt = 0; mt < 2; mt++)
                #pragma unroll
                for (int nt = 0; nt < 4; nt++)
                    mma_tf32_16n8k8(acc[mt][nt], afr[mt], bfr[nt], acc[mt][nt]);
        }
        __syncthreads();
    }

    // epilogue: relu(acc + c0[row] * feat[bn[row]][col]), float2 granularity
    #pragma unroll
    for (int mt = 0; mt < 2; mt++) {
        #pragma unroll
        for (int half = 0; half < 2; half++) {
            const int gr = bm0 + wm * 32 + mt * 16 + g + half * 8;
            if (gr >= B) continue;
            const int   node = bn[gr];
            const float cc   = g_c0[gr];
            #pragma unroll
            for (int nt = 0; nt < 4; nt++) {
                const int gc = bn0 + wn * 32 + nt * 8 + tig * 2;
                float2 h2 = *reinterpret_cast<const float2*>(
                                &feat[(size_t)node * NF + gc]);
                float2 r;
                r.x = fmaxf(acc[mt][nt][half * 2 + 0] + cc * h2.x, 0.0f);
                r.y = fmaxf(acc[mt][nt][half * 2 + 1] + cc * h2.y, 0.0f);
                *reinterpret_cast<float2*>(&out[(size_t)gr * NF + gc]) = r;
            }
        }
    }
}

// ---------------------------------------------------------------------------
extern "C" void kernel_launch(void* const* d_in, const int* in_sizes, int n_in,
                              void* d_out, int out_size)
{
    const float* feat = (const float*)d_in[0];   // node_features [50000,256]
    const float* W    = (const float*)d_in[1];   // weight [256,256]
    const int*   adj  = (const int*)d_in[2];     // adj [50000,32]
    const int*   bn   = (const int*)d_in[3];     // batch_nodes [B]
    float*       out  = (float*)d_out;

    const int B = in_sizes[3];

    subgraph_kernel<<<B, 256>>>(feat, adj, bn, B);

    dim3 grid(NF / BN, (B + BM - 1) / BM);
    gemm_kernel<<<grid, 256>>>(W, feat, bn, out, B);
}